// round 11
// baseline (speedup 1.0000x reference)
#include <cuda_runtime.h>
#include <cuda_bf16.h>

// GraphSAGE 2-layer, N=100000, E=1600000, D=128.
// R11: R10 (best, 565.9us) + (a) aggregation 8-wide load unroll (deeper MLP),
// (b) CSR build reads edge buffer directly in both passes (g_src/g_dst
// round-trip removed). GEMM unchanged (at FFMA2 roofline).

#define N_NODES 100000
#define N_EDGES 1600000
#define DFEAT   128
#define SCAN_BLK 1024
#define MAX_SCAN_BLOCKS ((N_NODES + SCAN_BLK - 1) / SCAN_BLK + 1)

// ---------------- scratch (device globals; no allocation allowed) ----------
__device__ int   g_is_i64;
__device__ int   g_cursor[N_NODES];
__device__ int   g_rowptr[N_NODES + 1];
__device__ int   g_col[N_EDGES];
__device__ int   g_bsum[MAX_SCAN_BLOCKS];
__device__ float g_mean[(size_t)N_NODES * DFEAT];
__device__ float g_h[(size_t)N_NODES * DFEAT];

// ---------------- small helpers -------------------------------------------
__device__ __forceinline__ unsigned long long dup_f32x2(float a) {
    unsigned long long r;
    asm("mov.b64 %0, {%1, %1};" : "=l"(r) : "f"(a));
    return r;
}
__device__ __forceinline__ void unpack_f32x2(unsigned long long v, float& lo, float& hi) {
    asm("mov.b64 {%0, %1}, %2;" : "=f"(lo), "=f"(hi) : "l"(v));
}
#define FFMA2(d, a, b, c) \
    asm("fma.rn.f32x2 %0, %1, %2, %3;" : "=l"(d) : "l"(a), "l"(b), "l"(c))

__device__ __forceinline__ int clamp_node(int v, int n) {
    unsigned u = (unsigned)v;
    return (u < (unsigned)n) ? v : 0;
}

// read (src,dst) of edge e straight from the raw edge words
__device__ __forceinline__ void load_edge(const int* __restrict__ ew, int e,
                                          int nedges, int nnodes,
                                          int& s, int& d) {
    if (g_is_i64) {
        s = ew[2 * (size_t)e];
        d = ew[2 * ((size_t)nedges + e)];
    } else {
        s = ew[e];
        d = ew[(size_t)nedges + e];
    }
    s = clamp_node(s, nnodes);
    d = clamp_node(d, nnodes);
}

// ---------------- edge dtype detect ----------------------------------------
__global__ void detect_kernel(const int* __restrict__ ew) {
    int flag = 0;
    for (int i = 1; i < 128; i += 2) flag |= ew[i];
    g_is_i64 = (flag == 0) ? 1 : 0;
}

__global__ void count_kernel(const int* __restrict__ ew, int nedges, int nnodes) {
    int e = blockIdx.x * blockDim.x + threadIdx.x;
    if (e >= nedges) return;
    int s, d;
    load_edge(ew, e, nedges, nnodes, s, d);
    atomicAdd(&g_cursor[d], 1);
}

__global__ void zero_int_kernel(int* p, int n) {
    int i = blockIdx.x * blockDim.x + threadIdx.x;
    if (i < n) p[i] = 0;
}

// ---------------- parallel scan: 3 phases ----------------------------------
__global__ void __launch_bounds__(SCAN_BLK)
scan_partial_kernel(int n) {
    __shared__ int warp_sums[32];
    int i = blockIdx.x * SCAN_BLK + threadIdx.x;
    int lane = threadIdx.x & 31;
    int wid = threadIdx.x >> 5;
    int v = (i < n) ? g_cursor[i] : 0;
    int x = v;
#pragma unroll
    for (int o = 1; o < 32; o <<= 1) {
        int y = __shfl_up_sync(0xffffffffu, x, o);
        if (lane >= o) x += y;
    }
    if (lane == 31) warp_sums[wid] = x;
    __syncthreads();
    if (wid == 0) {
        int s = warp_sums[lane];
#pragma unroll
        for (int o = 1; o < 32; o <<= 1) {
            int y = __shfl_up_sync(0xffffffffu, s, o);
            if (lane >= o) s += y;
        }
        warp_sums[lane] = s;
    }
    __syncthreads();
    int base = (wid > 0) ? warp_sums[wid - 1] : 0;
    if (i < n) g_rowptr[i] = base + x - v;
    if (threadIdx.x == SCAN_BLK - 1) g_bsum[blockIdx.x] = base + x;
}

__global__ void __launch_bounds__(SCAN_BLK)
scan_bsums_kernel(int nblocks, int n) {
    __shared__ int warp_sums[32];
    int t = threadIdx.x;
    int lane = t & 31;
    int wid = t >> 5;
    int v = (t < nblocks) ? g_bsum[t] : 0;
    int x = v;
#pragma unroll
    for (int o = 1; o < 32; o <<= 1) {
        int y = __shfl_up_sync(0xffffffffu, x, o);
        if (lane >= o) x += y;
    }
    if (lane == 31) warp_sums[wid] = x;
    __syncthreads();
    if (wid == 0) {
        int s = warp_sums[lane];
#pragma unroll
        for (int o = 1; o < 32; o <<= 1) {
            int y = __shfl_up_sync(0xffffffffu, s, o);
            if (lane >= o) s += y;
        }
        warp_sums[lane] = s;
    }
    __syncthreads();
    int base = (wid > 0) ? warp_sums[wid - 1] : 0;
    if (t < nblocks) g_bsum[t] = base + x - v;
    if (t == SCAN_BLK - 1) g_rowptr[n] = base + x;
}

__global__ void __launch_bounds__(SCAN_BLK)
scan_add_kernel(int n) {
    int i = blockIdx.x * SCAN_BLK + threadIdx.x;
    if (i >= n) return;
    g_rowptr[i] += g_bsum[blockIdx.x];
    g_cursor[i] = 0;
}

__global__ void fill_csr_kernel(const int* __restrict__ ew, int nedges, int nnodes) {
    int e = blockIdx.x * blockDim.x + threadIdx.x;
    if (e >= nedges) return;
    int s, d;
    load_edge(ew, e, nedges, nnodes, s, d);
    int pos = g_rowptr[d] + atomicAdd(&g_cursor[d], 1);
    g_col[pos] = s;
}

// ---------------- mean aggregation: one warp per node, 8-wide MLP ----------
__global__ void agg_mean_kernel(const float* __restrict__ feat, int nnodes) {
    int gwarp = (blockIdx.x * blockDim.x + threadIdx.x) >> 5;
    int lane = threadIdx.x & 31;
    if (gwarp >= nnodes) return;

    int start = g_rowptr[gwarp];
    int end = g_rowptr[gwarp + 1];
    float ax = 0.f, ay = 0.f, az = 0.f, aw = 0.f;
    int lane4 = lane * 4;

    for (int base = start; base < end; base += 32) {
        int m = min(32, end - base);
        int sv = (lane < m) ? g_col[base + lane] : 0;
        int kk = 0;
        for (; kk + 8 <= m; kk += 8) {
            int s0 = __shfl_sync(0xffffffffu, sv, kk);
            int s1 = __shfl_sync(0xffffffffu, sv, kk + 1);
            int s2 = __shfl_sync(0xffffffffu, sv, kk + 2);
            int s3 = __shfl_sync(0xffffffffu, sv, kk + 3);
            int s4 = __shfl_sync(0xffffffffu, sv, kk + 4);
            int s5 = __shfl_sync(0xffffffffu, sv, kk + 5);
            int s6 = __shfl_sync(0xffffffffu, sv, kk + 6);
            int s7 = __shfl_sync(0xffffffffu, sv, kk + 7);
            float4 v0 = *reinterpret_cast<const float4*>(feat + (size_t)s0 * DFEAT + lane4);
            float4 v1 = *reinterpret_cast<const float4*>(feat + (size_t)s1 * DFEAT + lane4);
            float4 v2 = *reinterpret_cast<const float4*>(feat + (size_t)s2 * DFEAT + lane4);
            float4 v3 = *reinterpret_cast<const float4*>(feat + (size_t)s3 * DFEAT + lane4);
            float4 v4 = *reinterpret_cast<const float4*>(feat + (size_t)s4 * DFEAT + lane4);
            float4 v5 = *reinterpret_cast<const float4*>(feat + (size_t)s5 * DFEAT + lane4);
            float4 v6 = *reinterpret_cast<const float4*>(feat + (size_t)s6 * DFEAT + lane4);
            float4 v7 = *reinterpret_cast<const float4*>(feat + (size_t)s7 * DFEAT + lane4);
            ax += ((v0.x + v1.x) + (v2.x + v3.x)) + ((v4.x + v5.x) + (v6.x + v7.x));
            ay += ((v0.y + v1.y) + (v2.y + v3.y)) + ((v4.y + v5.y) + (v6.y + v7.y));
            az += ((v0.z + v1.z) + (v2.z + v3.z)) + ((v4.z + v5.z) + (v6.z + v7.z));
            aw += ((v0.w + v1.w) + (v2.w + v3.w)) + ((v4.w + v5.w) + (v6.w + v7.w));
        }
        for (; kk < m; ++kk) {
            int s = __shfl_sync(0xffffffffu, sv, kk);
            float4 v = *reinterpret_cast<const float4*>(feat + (size_t)s * DFEAT + lane4);
            ax += v.x; ay += v.y; az += v.z; aw += v.w;
        }
    }
    float inv = 1.f / fmaxf((float)(end - start), 1.f);
    float4 o;
    o.x = ax * inv; o.y = ay * inv; o.z = az * inv; o.w = aw * inv;
    *reinterpret_cast<float4*>(g_mean + (size_t)gwarp * DFEAT + lane4) = o;
}

// ---------------- persistent fused SAGE GEMM (128-node tiles) ---------------
// out[n][j] = sum_k mean[n][k]*Wl[j][k] + sum_k feat[n][k]*Wr[j][k] + b[j]
// grid=148 persistent CTAs x 512 threads; weights resident; 128-node tiles;
// double-buffered dup-A staging; inner loop: 4x uniform LDS.128 (A) +
// 1x LDS.128 (W) + 16x FFMA2 per k -> fma-pipe bound.
#define W_STRIDE 132
#define GTILE    128
#define GEMM_SMEM (256 * W_STRIDE * 4 + 2 * 32 * 128 * 8)

__global__ void __launch_bounds__(512)
sage_gemm_kernel(const float* __restrict__ A0,   // mean  (k = 0..127)
                 const float* __restrict__ A1,   // feat  (k = 128..255)
                 const float* __restrict__ Wl,
                 const float* __restrict__ Wr,
                 const float* __restrict__ bias,
                 float* __restrict__ out,
                 int nnodes, int relu, int ntiles) {
    extern __shared__ float smem[];
    float* sW = smem;                                                   // 256*132
    unsigned long long* sA2 =
        reinterpret_cast<unsigned long long*>(smem + 256 * W_STRIDE);   // 2*32*128

    int tid = threadIdx.x;
    // Load + transpose weights ONCE per CTA.
    for (int idx = tid; idx < 128 * 128; idx += 512) {
        int j = idx >> 7;
        int k = idx & 127;
        sW[k * W_STRIDE + j] = Wl[idx];
        sW[(k + 128) * W_STRIDE + j] = Wr[idx];
    }

    int lane = tid & 31;
    int warp = tid >> 5;
    int j0 = lane * 4;

    // staging role: thread loads 8 k-values (two float4) of one node per chunk
    int st_node = tid >> 2;           // 0..127
    int st_q = tid & 3;               // 0..3 -> k offsets q*8..q*8+7
    int kb = st_q * 8;

    // bias packed once
    float4 bv = *reinterpret_cast<const float4*>(bias + j0);
    unsigned long long b01, b23;
    asm("mov.b64 %0, {%1, %2};" : "=l"(b01) : "f"(bv.x), "f"(bv.y));
    asm("mov.b64 %0, {%1, %2};" : "=l"(b23) : "f"(bv.z), "f"(bv.w));

    for (int tile = blockIdx.x; tile < ntiles; tile += gridDim.x) {
        int base_node = tile * GTILE;
        int st_gnode = base_node + st_node;
        if (st_gnode >= nnodes) st_gnode = nnodes - 1;
        const float* a0p = A0 + (size_t)st_gnode * DFEAT + st_q * 8;
        const float* a1p = A1 + (size_t)st_gnode * DFEAT + st_q * 8;

        // prefetch chunk 0
        float4 v0 = *reinterpret_cast<const float4*>(a0p);
        float4 v1 = *reinterpret_cast<const float4*>(a0p + 4);

        unsigned long long acc[16];
#pragma unroll
        for (int m = 0; m < 8; ++m) { acc[2 * m] = b01; acc[2 * m + 1] = b23; }

        for (int c = 0; c < 8; ++c) {
            unsigned long long* buf = sA2 + (c & 1) * (32 * 128);
            buf[(kb + 0) * 128 + st_node] = dup_f32x2(v0.x);
            buf[(kb + 1) * 128 + st_node] = dup_f32x2(v0.y);
            buf[(kb + 2) * 128 + st_node] = dup_f32x2(v0.z);
            buf[(kb + 3) * 128 + st_node] = dup_f32x2(v0.w);
            buf[(kb + 4) * 128 + st_node] = dup_f32x2(v1.x);
            buf[(kb + 5) * 128 + st_node] = dup_f32x2(v1.y);
            buf[(kb + 6) * 128 + st_node] = dup_f32x2(v1.z);
            buf[(kb + 7) * 128 + st_node] = dup_f32x2(v1.w);

            if (c + 1 < 8) {
                int cn = c + 1;
                const float* ap = (cn < 4) ? a0p : a1p;
                int koff = (cn & 3) * 32;
                v0 = *reinterpret_cast<const float4*>(ap + koff);
                v1 = *reinterpret_cast<const float4*>(ap + koff + 4);
            }
            __syncthreads();

            int krow = c * 32;
            const unsigned long long* aw_base = buf + warp * 8;
#pragma unroll 4
            for (int kk = 0; kk < 32; ++kk) {
                ulonglong2 wv = *reinterpret_cast<const ulonglong2*>(
                    &sW[(krow + kk) * W_STRIDE + j0]);
                const ulonglong2* ar2 =
                    reinterpret_cast<const ulonglong2*>(aw_base + kk * 128);
                ulonglong2 a01 = ar2[0];
                ulonglong2 a23 = ar2[1];
                ulonglong2 a45 = ar2[2];
                ulonglong2 a67 = ar2[3];
                FFMA2(acc[0],  a01.x, wv.x, acc[0]);
                FFMA2(acc[1],  a01.x, wv.y, acc[1]);
                FFMA2(acc[2],  a01.y, wv.x, acc[2]);
                FFMA2(acc[3],  a01.y, wv.y, acc[3]);
                FFMA2(acc[4],  a23.x, wv.x, acc[4]);
                FFMA2(acc[5],  a23.x, wv.y, acc[5]);
                FFMA2(acc[6],  a23.y, wv.x, acc[6]);
                FFMA2(acc[7],  a23.y, wv.y, acc[7]);
                FFMA2(acc[8],  a45.x, wv.x, acc[8]);
                FFMA2(acc[9],  a45.x, wv.y, acc[9]);
                FFMA2(acc[10], a45.y, wv.x, acc[10]);
                FFMA2(acc[11], a45.y, wv.y, acc[11]);
                FFMA2(acc[12], a67.x, wv.x, acc[12]);
                FFMA2(acc[13], a67.x, wv.y, acc[13]);
                FFMA2(acc[14], a67.y, wv.x, acc[14]);
                FFMA2(acc[15], a67.y, wv.y, acc[15]);
            }
        }

        int wnode = base_node + warp * 8;
#pragma unroll
        for (int m = 0; m < 8; ++m) {
            int nd = wnode + m;
            if (nd >= nnodes) break;
            float4 o;
            unpack_f32x2(acc[2 * m], o.x, o.y);
            unpack_f32x2(acc[2 * m + 1], o.z, o.w);
            if (relu) {
                o.x = fmaxf(o.x, 0.f); o.y = fmaxf(o.y, 0.f);
                o.z = fmaxf(o.z, 0.f); o.w = fmaxf(o.w, 0.f);
            }
            *reinterpret_cast<float4*>(out + (size_t)nd * DFEAT + j0) = o;
        }
        __syncthreads();   // tile done before next staging overwrites buffers
    }
}

// ---------------- launch ----------------------------------------------------
extern "C" void kernel_launch(void* const* d_in, const int* in_sizes, int n_in,
                              void* d_out, int out_size) {
    const float* x   = (const float*)d_in[0];
    const int*   ew  = (const int*)d_in[1];
    const float* Wl1 = (const float*)d_in[2];
    const float* bl1 = (const float*)d_in[3];
    const float* Wr1 = (const float*)d_in[4];
    const float* Wl2 = (const float*)d_in[5];
    const float* bl2 = (const float*)d_in[6];
    const float* Wr2 = (const float*)d_in[7];
    float*       out = (float*)d_out;

    int n = in_sizes[0] / DFEAT;      // 100000
    int e = in_sizes[1] / 2;          // 1600000

    void *p_mean_v, *p_h_v, *p_cursor_v;
    cudaGetSymbolAddress(&p_mean_v, g_mean);
    cudaGetSymbolAddress(&p_h_v, g_h);
    cudaGetSymbolAddress(&p_cursor_v, g_cursor);
    float* p_mean = (float*)p_mean_v;
    float* p_h = (float*)p_h_v;
    int* p_cursor = (int*)p_cursor_v;

    cudaFuncSetAttribute(sage_gemm_kernel,
                         cudaFuncAttributeMaxDynamicSharedMemorySize, GEMM_SMEM);

    int zb = (n + 255) / 256;
    int eb = (e + 255) / 256;
    int ab = (n + 7) / 8;
    int sb = (n + SCAN_BLK - 1) / SCAN_BLK;
    int ntiles = (n + GTILE - 1) / GTILE;

    // ---- CSR build: count -> scan -> fill (edge buffer read directly) ----
    detect_kernel<<<1, 1>>>(ew);
    zero_int_kernel<<<zb, 256>>>(p_cursor, n);
    count_kernel<<<eb, 256>>>(ew, e, n);

    scan_partial_kernel<<<sb, SCAN_BLK>>>(n);
    scan_bsums_kernel<<<1, SCAN_BLK>>>(sb, n);
    scan_add_kernel<<<sb, SCAN_BLK>>>(n);

    fill_csr_kernel<<<eb, 256>>>(ew, e, n);

    // ---- layer 1 ----
    agg_mean_kernel<<<ab, 256>>>(x, n);
    sage_gemm_kernel<<<148, 512, GEMM_SMEM>>>(p_mean, x, Wl1, Wr1, bl1, p_h, n, 1, ntiles);

    // ---- layer 2 ----
    agg_mean_kernel<<<ab, 256>>>(p_h, n);
    sage_gemm_kernel<<<148, 512, GEMM_SMEM>>>(p_mean, p_h, Wl2, Wr2, bl2, out, n, 0, ntiles);
}